// round 1
// baseline (speedup 1.0000x reference)
#include <cuda_runtime.h>
#include <cstdint>
#include <cstdio>

#define NB 256   // batch

// ---------------- scratch (device globals; no allocation) ----------------
__device__ float g_h1 [(size_t)NB*32*32*32];   // NCHW
__device__ float g_h1n[(size_t)NB*32*32*32];   // NHWC
__device__ float g_off2[(size_t)NB*18*16*16];
__device__ float g_h2 [(size_t)NB*64*16*16];
__device__ float g_h2n[(size_t)NB*64*16*16];
__device__ float g_off3[(size_t)NB*18*16*16];
__device__ float g_h3 [(size_t)NB*128*16*16];
__device__ float g_h3n[(size_t)NB*128*16*16];
__device__ float g_off4[(size_t)NB*18*8*8];
__device__ float g_h4 [(size_t)NB*128*8*8];
__device__ float g_h4n[(size_t)NB*128*8*8];

// ---------------- conv1 (3->32, 3x3, pad 1) + BN + ReLU ----------------
__global__ __launch_bounds__(256) void conv1_kernel(
    const float* __restrict__ x, const float* __restrict__ w1, const float* __restrict__ b1,
    const float* __restrict__ g, const float* __restrict__ be,
    const float* __restrict__ m, const float* __restrict__ v,
    float* __restrict__ out_nchw, float* __restrict__ out_nhwc)
{
    __shared__ float s_w[32*27];
    __shared__ float s_sc[32], s_sh[32];
    __shared__ float s_o[256*33];   // padded to 33 to avoid bank conflicts

    int tid = threadIdx.x;
    for (int idx = tid; idx < 32*27; idx += 256) s_w[idx] = w1[idx];
    if (tid < 32) {
        float sc = g[tid] / sqrtf(v[tid] + 1e-5f);
        s_sc[tid] = sc;
        s_sh[tid] = be[tid] - m[tid]*sc + b1[tid]*sc;
    }
    __syncthreads();

    int q = blockIdx.x * 256 + tid;     // position over NB*32*32
    int b = q >> 10;
    int p = q & 1023;
    int i = p >> 5, j = p & 31;

    float in[27];
    const float* xb = x + (size_t)b * 3 * 1024;
    #pragma unroll
    for (int c = 0; c < 3; c++)
        #pragma unroll
        for (int ky = 0; ky < 3; ky++)
            #pragma unroll
            for (int kx = 0; kx < 3; kx++) {
                int yy = i - 1 + ky, xx = j - 1 + kx;
                float val = 0.f;
                if ((unsigned)yy < 32u && (unsigned)xx < 32u)
                    val = xb[c*1024 + yy*32 + xx];
                in[c*9 + ky*3 + kx] = val;
            }

    #pragma unroll
    for (int oc = 0; oc < 32; oc++) {
        float a = 0.f;
        #pragma unroll
        for (int k = 0; k < 27; k++) a += in[k] * s_w[oc*27 + k];
        float val = fmaxf(a * s_sc[oc] + s_sh[oc], 0.f);
        out_nchw[((size_t)b*32 + oc)*1024 + p] = val;
        s_o[tid*33 + oc] = val;
    }
    __syncthreads();

    size_t base = (size_t)blockIdx.x * 256 * 32;
    for (int idx = tid; idx < 256*32; idx += 256) {
        int pp = idx >> 5, oc = idx & 31;
        out_nhwc[base + idx] = s_o[pp*33 + oc];
    }
}

// ---------------- offset conv: C -> 18, 3x3, pad 1, stride S ----------------
template<int C, int S, int H, int W>
__global__ __launch_bounds__(256) void offconv_kernel(
    const float* __restrict__ feat,   // NCHW
    const float* __restrict__ wp, const float* __restrict__ bp,
    float* __restrict__ off)
{
    constexpr int h = (H - 1) / S + 1;
    constexpr int w = (W - 1) / S + 1;
    constexpr int HW = h * w;

    extern __shared__ float s_w[];    // 18*C*9
    __shared__ float s_b[18];
    for (int idx = threadIdx.x; idx < 18*C*9; idx += 256) s_w[idx] = wp[idx];
    if (threadIdx.x < 18) s_b[threadIdx.x] = bp[threadIdx.x];
    __syncthreads();

    int q = blockIdx.x * 256 + threadIdx.x;   // over NB*HW (exact multiple)
    int b = q / HW;
    int p = q - b * HW;
    int i = p / w, j = p - i * w;

    float acc[18];
    #pragma unroll
    for (int ch = 0; ch < 18; ch++) acc[ch] = s_b[ch];

    for (int c = 0; c < C; c++) {
        const float* fc = feat + ((size_t)b*C + c) * (H*W);
        #pragma unroll
        for (int ky = 0; ky < 3; ky++) {
            int yy = i*S - 1 + ky;
            if ((unsigned)yy >= (unsigned)H) continue;
            #pragma unroll
            for (int kx = 0; kx < 3; kx++) {
                int xx = j*S - 1 + kx;
                if ((unsigned)xx >= (unsigned)W) continue;
                float val = fc[yy*W + xx];
                #pragma unroll
                for (int ch = 0; ch < 18; ch++)
                    acc[ch] += val * s_w[(ch*C + c)*9 + ky*3 + kx];
            }
        }
    }
    #pragma unroll
    for (int ch = 0; ch < 18; ch++)
        off[((size_t)b*18 + ch)*HW + p] = acc[ch];
}

// ---------------- deform sample + GEMM + BN + ReLU ----------------
// feat_nhwc: (B,H,W,C); off: (B,18,h,w); wc: (O, C*9); outputs NCHW + NHWC
template<int C, int O, int S, int H, int W, int TILE>
__global__ __launch_bounds__(256) void deform_kernel(
    const float* __restrict__ feat_nhwc,
    const float* __restrict__ off,
    const float* __restrict__ wc,
    const float* __restrict__ g, const float* __restrict__ be,
    const float* __restrict__ m, const float* __restrict__ v,
    float* __restrict__ out_nchw, float* __restrict__ out_nhwc)
{
    constexpr int K  = C * 9;
    constexpr int h  = (H - 1) / S + 1;
    constexpr int w  = (W - 1) / S + 1;
    constexpr int HW = h * w;
    constexpr int KC = 32;
    constexpr int OPT = O / 64;    // outputs per thread (1 or 2)

    extern __shared__ float sm[];
    float* s_x = sm;                               // TILE*K  (reused as s_out)
    float* s_g = s_x + TILE*K;                     // TILE*9*4
    int*   s_q = (int*)(s_g + TILE*9*4);           // TILE*9*4
    float* s_w = (float*)(s_q + TILE*9*4);         // KC*(O+1)

    int tid = threadIdx.x;
    int bidx = blockIdx.x;
    int b = bidx / (HW / TILE);
    int pbase = (bidx % (HW / TILE)) * TILE;

    // ---- Phase A: bilinear metas for TILE*9 samples ----
    if (tid < TILE*9) {
        int t = tid / 9, n = tid - t*9;
        int p = pbase + t;
        int i = p / w, j = p - i*w;
        float offx = off[((size_t)(b*18 + n)    )*HW + p];
        float offy = off[((size_t)(b*18 + 9 + n))*HW + p];
        float px = (float)(1 + i*S + (n/3) - 1) + offx;
        float py = (float)(1 + j*S + (n%3) - 1) + offy;
        const float HB = (float)(H + 1), WB = (float)(W + 1);
        float qx0 = floorf(px);
        float fx0 = fminf(fmaxf(qx0,       0.f), HB);
        float fx1 = fminf(fmaxf(qx0 + 1.f, 0.f), HB);
        float pxc = fminf(fmaxf(px,        0.f), HB);
        float qy0 = floorf(py);
        float fy0 = fminf(fmaxf(qy0,       0.f), WB);
        float fy1 = fminf(fmaxf(qy0 + 1.f, 0.f), WB);
        float pyc = fminf(fmaxf(py,        0.f), WB);
        float glt = (1.f + (fx0 - pxc)) * (1.f + (fy0 - pyc));
        float grb = (1.f - (fx1 - pxc)) * (1.f - (fy1 - pyc));
        float glb = (1.f + (fx0 - pxc)) * (1.f - (fy1 - pyc));
        float grt = (1.f - (fx1 - pxc)) * (1.f + (fy0 - pyc));
        s_g[tid*4+0] = glt; s_g[tid*4+1] = grb;
        s_g[tid*4+2] = glb; s_g[tid*4+3] = grt;
        s_q[tid*4+0] = (int)fx0; s_q[tid*4+1] = (int)fx1;
        s_q[tid*4+2] = (int)fy0; s_q[tid*4+3] = (int)fy1;
    }
    __syncthreads();

    // ---- Phase B: gather x_off tile [TILE][K], k = c*9+n ----
    const float* fb = feat_nhwc + (size_t)b * H * W * C;
    for (int idx = tid; idx < TILE*9*C; idx += 256) {
        int tn = idx / C;
        int c  = idx - tn * C;
        int x0 = s_q[tn*4+0], x1 = s_q[tn*4+1];
        int y0 = s_q[tn*4+2], y1 = s_q[tn*4+3];
        float g0 = s_g[tn*4+0], g1 = s_g[tn*4+1];
        float g2 = s_g[tn*4+2], g3 = s_g[tn*4+3];
        float v00 = 0.f, v11 = 0.f, v01 = 0.f, v10 = 0.f;
        bool bx0 = (x0 >= 1 && x0 <= H), bx1 = (x1 >= 1 && x1 <= H);
        bool by0 = (y0 >= 1 && y0 <= W), by1 = (y1 >= 1 && y1 <= W);
        if (bx0 && by0) v00 = fb[((size_t)(x0-1)*W + (y0-1))*C + c];
        if (bx1 && by1) v11 = fb[((size_t)(x1-1)*W + (y1-1))*C + c];
        if (bx0 && by1) v01 = fb[((size_t)(x0-1)*W + (y1-1))*C + c];
        if (bx1 && by0) v10 = fb[((size_t)(x1-1)*W + (y0-1))*C + c];
        float val = g0*v00 + g1*v11 + g2*v01 + g3*v10;
        int t = tn / 9, n = tn - t*9;
        s_x[t*K + c*9 + n] = val;
    }
    __syncthreads();

    // ---- Phase C: GEMM out[t][o] = sum_k x[t][k] * wc[o][k] ----
    int tg = tid >> 6;        // 4 t-groups of 4 positions
    int lo = tid & 63;        // 64 threads per t-group
    float acc[4][OPT];
    #pragma unroll
    for (int tt = 0; tt < 4; tt++)
        #pragma unroll
        for (int oi = 0; oi < OPT; oi++) acc[tt][oi] = 0.f;

    for (int k0 = 0; k0 < K; k0 += KC) {
        for (int idx = tid; idx < O*KC; idx += 256) {
            int o = idx >> 5, kc = idx & 31;
            s_w[kc*(O+1) + o] = wc[(size_t)o*K + k0 + kc];
        }
        __syncthreads();
        #pragma unroll 8
        for (int kc = 0; kc < KC; kc++) {
            float xv[4];
            #pragma unroll
            for (int tt = 0; tt < 4; tt++)
                xv[tt] = s_x[(tg*4 + tt)*K + k0 + kc];
            #pragma unroll
            for (int oi = 0; oi < OPT; oi++) {
                float wv = s_w[kc*(O+1) + lo + 64*oi];
                #pragma unroll
                for (int tt = 0; tt < 4; tt++)
                    acc[tt][oi] += xv[tt] * wv;
            }
        }
        __syncthreads();
    }

    // ---- Epilogue: BN + ReLU, stage, coalesced dual-layout stores ----
    float sc[OPT], sh[OPT];
    #pragma unroll
    for (int oi = 0; oi < OPT; oi++) {
        int o = lo + 64*oi;
        float s = g[o] / sqrtf(v[o] + 1e-5f);
        sc[oi] = s;
        sh[oi] = be[o] - m[o]*s;
    }
    float* s_o = s_x;   // reuse (all reads of s_x completed)
    #pragma unroll
    for (int tt = 0; tt < 4; tt++)
        #pragma unroll
        for (int oi = 0; oi < OPT; oi++) {
            float val = fmaxf(acc[tt][oi]*sc[oi] + sh[oi], 0.f);
            s_o[(tg*4 + tt)*(O+1) + lo + 64*oi] = val;
        }
    __syncthreads();

    for (int idx = tid; idx < TILE*O; idx += 256) {        // NHWC
        int t = idx / O, o = idx - t*O;
        out_nhwc[((size_t)b*HW + pbase + t)*O + o] = s_o[t*(O+1) + o];
    }
    for (int idx = tid; idx < TILE*O; idx += 256) {        // NCHW
        int o = idx / TILE, t = idx - o*TILE;
        out_nchw[((size_t)b*O + o)*HW + pbase + t] = s_o[t*(O+1) + o];
    }
}

// ---------------- global avg pool (8x8) + FC (128 -> 100) ----------------
__global__ __launch_bounds__(128) void poolfc_kernel(
    const float* __restrict__ h4,    // NCHW (B,128,8,8)
    const float* __restrict__ wcls, const float* __restrict__ bcls,
    float* __restrict__ out)
{
    __shared__ float s_p[128];
    int b = blockIdx.x, tid = threadIdx.x;
    const float* hb = h4 + ((size_t)b*128 + tid) * 64;
    float s = 0.f;
    #pragma unroll
    for (int k = 0; k < 64; k++) s += hb[k];
    s_p[tid] = s * (1.f / 64.f);
    __syncthreads();
    if (tid < 100) {
        float a = bcls[tid];
        const float* wr = wcls + tid*128;
        #pragma unroll 16
        for (int o = 0; o < 128; o++) a += s_p[o] * wr[o];
        out[b*100 + tid] = a;
    }
}

// ---------------- launch ----------------
extern "C" void kernel_launch(void* const* d_in, const int* in_sizes, int n_in,
                              void* d_out, int out_size)
{
    (void)in_sizes; (void)n_in; (void)out_size;
    const float* x    = (const float*)d_in[0];
    const float* w1   = (const float*)d_in[1];
    const float* b1   = (const float*)d_in[2];
    const float* g1   = (const float*)d_in[3];
    const float* be1  = (const float*)d_in[4];
    const float* m1   = (const float*)d_in[5];
    const float* v1   = (const float*)d_in[6];
    const float* wp2  = (const float*)d_in[7];
    const float* bp2  = (const float*)d_in[8];
    const float* wc2  = (const float*)d_in[9];
    const float* g2   = (const float*)d_in[10];
    const float* be2  = (const float*)d_in[11];
    const float* m2   = (const float*)d_in[12];
    const float* v2   = (const float*)d_in[13];
    const float* wp3  = (const float*)d_in[14];
    const float* bp3  = (const float*)d_in[15];
    const float* wc3  = (const float*)d_in[16];
    const float* g3   = (const float*)d_in[17];
    const float* be3  = (const float*)d_in[18];
    const float* m3   = (const float*)d_in[19];
    const float* v3   = (const float*)d_in[20];
    const float* wp4  = (const float*)d_in[21];
    const float* bp4  = (const float*)d_in[22];
    const float* wc4  = (const float*)d_in[23];
    const float* g4   = (const float*)d_in[24];
    const float* be4  = (const float*)d_in[25];
    const float* m4   = (const float*)d_in[26];
    const float* v4   = (const float*)d_in[27];
    const float* wcls = (const float*)d_in[28];
    const float* bcls = (const float*)d_in[29];
    float* out = (float*)d_out;

    float *h1, *h1n, *off2, *h2, *h2n, *off3, *h3, *h3n, *off4, *h4, *h4n;
    cudaGetSymbolAddress((void**)&h1,  g_h1);
    cudaGetSymbolAddress((void**)&h1n, g_h1n);
    cudaGetSymbolAddress((void**)&off2,g_off2);
    cudaGetSymbolAddress((void**)&h2,  g_h2);
    cudaGetSymbolAddress((void**)&h2n, g_h2n);
    cudaGetSymbolAddress((void**)&off3,g_off3);
    cudaGetSymbolAddress((void**)&h3,  g_h3);
    cudaGetSymbolAddress((void**)&h3n, g_h3n);
    cudaGetSymbolAddress((void**)&off4,g_off4);
    cudaGetSymbolAddress((void**)&h4,  g_h4);
    cudaGetSymbolAddress((void**)&h4n, g_h4n);

    // L1: conv1 + BN + ReLU
    conv1_kernel<<<NB*1024/256, 256>>>(x, w1, b1, g1, be1, m1, v1, h1, h1n);

    // L2: offsets + deform (32 -> 64, stride 2, 32x32 -> 16x16)
    {
        size_t sm = 18*32*9*sizeof(float);
        offconv_kernel<32,2,32,32><<<NB*256/256, 256, sm>>>(h1, wp2, bp2, off2);
        constexpr int K = 32*9, TILE = 16, O = 64;
        size_t dsm = (size_t)(TILE*K + TILE*9*8 + 32*(O+1)) * sizeof(float);
        cudaFuncSetAttribute(deform_kernel<32,64,2,32,32,16>,
                             cudaFuncAttributeMaxDynamicSharedMemorySize, (int)dsm);
        deform_kernel<32,64,2,32,32,16><<<NB*256/TILE, 256, dsm>>>(
            h1n, off2, wc2, g2, be2, m2, v2, h2, h2n);
    }
    // L3: offsets + deform (64 -> 128, stride 1, 16x16 -> 16x16)
    {
        size_t sm = 18*64*9*sizeof(float);
        offconv_kernel<64,1,16,16><<<NB*256/256, 256, sm>>>(h2, wp3, bp3, off3);
        constexpr int K = 64*9, TILE = 16, O = 128;
        size_t dsm = (size_t)(TILE*K + TILE*9*8 + 32*(O+1)) * sizeof(float);
        cudaFuncSetAttribute(deform_kernel<64,128,1,16,16,16>,
                             cudaFuncAttributeMaxDynamicSharedMemorySize, (int)dsm);
        deform_kernel<64,128,1,16,16,16><<<NB*256/TILE, 256, dsm>>>(
            h2n, off3, wc3, g3, be3, m3, v3, h3, h3n);
    }
    // L4: offsets + deform (128 -> 128, stride 2, 16x16 -> 8x8)
    {
        size_t sm = 18*128*9*sizeof(float);
        cudaFuncSetAttribute(offconv_kernel<128,2,16,16>,
                             cudaFuncAttributeMaxDynamicSharedMemorySize, (int)sm);
        offconv_kernel<128,2,16,16><<<NB*64/256, 256, sm>>>(h3, wp4, bp4, off4);
        constexpr int K = 128*9, TILE = 16, O = 128;
        size_t dsm = (size_t)(TILE*K + TILE*9*8 + 32*(O+1)) * sizeof(float);
        cudaFuncSetAttribute(deform_kernel<128,128,2,16,16,16>,
                             cudaFuncAttributeMaxDynamicSharedMemorySize, (int)dsm);
        deform_kernel<128,128,2,16,16,16><<<NB*64/TILE, 256, dsm>>>(
            h3n, off4, wc4, g4, be4, m4, v4, h4, h4n);
    }
    // pool + FC
    poolfc_kernel<<<NB, 128>>>(h4, wcls, bcls, out);
}

// round 2
// speedup vs baseline: 1.5927x; 1.5927x over previous
#include <cuda_runtime.h>
#include <cstdint>

#define NB 256   // batch

// ---------------- scratch (device globals; no allocation) ----------------
__device__ float g_h1n [(size_t)NB*32*32*32];   // NHWC
__device__ float g_off2[(size_t)NB*18*16*16];
__device__ float g_h2n [(size_t)NB*64*16*16];
__device__ float g_off3[(size_t)NB*18*16*16];
__device__ float g_h3n [(size_t)NB*128*16*16];
__device__ float g_off4[(size_t)NB*18*8*8];
__device__ float g_h4n [(size_t)NB*128*8*8];
__device__ float g_wt2 [64*288];                // wt[k][o], k = n*C+c
__device__ float g_wt3 [128*576];
__device__ float g_wt4 [128*1152];

// ---------------- f32x2 helpers ----------------
__device__ __forceinline__ unsigned long long pk2(float lo, float hi) {
    unsigned long long r;
    asm("mov.b64 %0, {%1, %2};" : "=l"(r) : "f"(lo), "f"(hi));
    return r;
}
__device__ __forceinline__ void fma2(unsigned long long& d,
                                     unsigned long long a, unsigned long long b) {
    asm("fma.rn.f32x2 %0, %1, %2, %0;" : "+l"(d) : "l"(a), "l"(b));
}
__device__ __forceinline__ unsigned long long add2(unsigned long long a,
                                                   unsigned long long b) {
    unsigned long long r;
    asm("add.rn.f32x2 %0, %1, %2;" : "=l"(r) : "l"(a), "l"(b));
    return r;
}
__device__ __forceinline__ float2 upk2(unsigned long long v) {
    float2 r;
    asm("mov.b64 {%0, %1}, %2;" : "=f"(r.x), "=f"(r.y) : "l"(v));
    return r;
}

// ---------------- weight transpose prep: wt[(n*C+c)*O+o] = wc[o][c][n] ----------------
__global__ void wprep_kernel(const float* __restrict__ wc, float* __restrict__ wt,
                             int O, int C) {
    int idx = blockIdx.x * 256 + threadIdx.x;
    int K = C * 9;
    if (idx < K * O) {
        int k = idx / O, o = idx - k * O;
        int n = k / C,  c = k - n * C;
        wt[idx] = wc[(o * C + c) * 9 + n];
    }
}

// ---------------- conv1 (3->32, 3x3, pad 1) + BN + ReLU -> NHWC ----------------
__global__ __launch_bounds__(256) void conv1_kernel(
    const float* __restrict__ x, const float* __restrict__ w1, const float* __restrict__ b1,
    const float* __restrict__ g, const float* __restrict__ be,
    const float* __restrict__ m, const float* __restrict__ v,
    float* __restrict__ out_nhwc)
{
    __shared__ float s_w[32*27];
    __shared__ float s_sc[32], s_sh[32];
    __shared__ float s_o[256*33];

    int tid = threadIdx.x;
    for (int idx = tid; idx < 32*27; idx += 256) s_w[idx] = w1[idx];
    if (tid < 32) {
        float sc = g[tid] / sqrtf(v[tid] + 1e-5f);
        s_sc[tid] = sc;
        s_sh[tid] = be[tid] - m[tid]*sc + b1[tid]*sc;
    }
    __syncthreads();

    int q = blockIdx.x * 256 + tid;
    int b = q >> 10;
    int p = q & 1023;
    int i = p >> 5, j = p & 31;

    float in[27];
    const float* xb = x + (size_t)b * 3 * 1024;
    #pragma unroll
    for (int c = 0; c < 3; c++)
        #pragma unroll
        for (int ky = 0; ky < 3; ky++)
            #pragma unroll
            for (int kx = 0; kx < 3; kx++) {
                int yy = i - 1 + ky, xx = j - 1 + kx;
                float val = 0.f;
                if ((unsigned)yy < 32u && (unsigned)xx < 32u)
                    val = xb[c*1024 + yy*32 + xx];
                in[c*9 + ky*3 + kx] = val;
            }

    #pragma unroll
    for (int oc = 0; oc < 32; oc++) {
        float a = 0.f;
        #pragma unroll
        for (int k = 0; k < 27; k++) a += in[k] * s_w[oc*27 + k];
        s_o[tid*33 + oc] = fmaxf(a * s_sc[oc] + s_sh[oc], 0.f);
    }
    __syncthreads();

    size_t base = (size_t)blockIdx.x * 256 * 32;
    for (int idx = tid; idx < 256*32; idx += 256) {
        int pp = idx >> 5, oc = idx & 31;
        out_nhwc[base + idx] = s_o[pp*33 + oc];
    }
}

// ---------------- offset conv: NHWC feat, C -> 18, 3x3, pad 1, stride S ----------------
// block = 32 positions x 8 channel-groups; shuffle-reduce over groups.
template<int C, int S, int H, int W>
__global__ __launch_bounds__(256) void offconv_v2(
    const float* __restrict__ feat_nhwc,
    const float* __restrict__ wp, const float* __restrict__ bp,
    float* __restrict__ off)
{
    constexpr int h = (H - 1) / S + 1;
    constexpr int w = (W - 1) / S + 1;
    constexpr int HW = h * w;

    extern __shared__ float s_w[];   // [(c*9+tap)*18 + ch], C*9*18 floats
    int tid = threadIdx.x;
    for (int idx = tid; idx < 18*C*9; idx += 256) {
        int ch = idx / (C*9);
        int r  = idx - ch * (C*9);   // r = c*9 + tap
        s_w[r*18 + ch] = wp[idx];
    }
    __syncthreads();

    int pl = tid >> 3;      // position in block: 0..31
    int cg = tid & 7;       // channel group
    int gpos = blockIdx.x * 32 + pl;
    int b = gpos / HW, p = gpos - b*HW;
    int i = p / w, j = p - i*w;
    const float* fb = feat_nhwc + (size_t)b * H * W * C;

    unsigned long long acc2[9];
    #pragma unroll
    for (int q = 0; q < 9; q++) acc2[q] = 0ull;

    #pragma unroll 2
    for (int ci = 0; ci < C/8; ci++) {
        int c = ci*8 + cg;
        float pv[9];
        #pragma unroll
        for (int ky = 0; ky < 3; ky++)
            #pragma unroll
            for (int kx = 0; kx < 3; kx++) {
                int yy = i*S - 1 + ky, xx = j*S - 1 + kx;
                float vv = 0.f;
                if ((unsigned)yy < (unsigned)H && (unsigned)xx < (unsigned)W)
                    vv = fb[((size_t)yy*W + xx)*C + c];
                pv[ky*3+kx] = vv;
            }
        const float* wr = s_w + c*162;   // c*9*18
        #pragma unroll
        for (int tap = 0; tap < 9; tap++) {
            unsigned long long pd = pk2(pv[tap], pv[tap]);
            const unsigned long long* wv =
                reinterpret_cast<const unsigned long long*>(wr + tap*18);
            #pragma unroll
            for (int chp = 0; chp < 9; chp++) fma2(acc2[chp], pd, wv[chp]);
        }
    }

    // reduce over the 8 channel-groups (lanes xor 1,2,4 within 8-lane clusters)
    #pragma unroll
    for (int d = 4; d >= 1; d >>= 1)
        #pragma unroll
        for (int q = 0; q < 9; q++)
            acc2[q] = add2(acc2[q], __shfl_xor_sync(0xffffffffu, acc2[q], d));

    if (cg == 0) {
        #pragma unroll
        for (int q = 0; q < 9; q++) {
            float2 r = upk2(acc2[q]);
            off[((size_t)(b*18 + 2*q    ))*HW + p] = r.x + bp[2*q];
            off[((size_t)(b*18 + 2*q + 1))*HW + p] = r.y + bp[2*q+1];
        }
    }
}

// ---------------- deform: gather + blocked SGEMM (f32x2) + BN + ReLU -> NHWC ----------------
// feat_nhwc: (B,H,W,C); off: (B,18,h,w); wt: [k][O] with k = n*C + c.
template<int C, int O, int S, int H, int W, int TILE_M>
__global__ __launch_bounds__(256, 2) void deform_v2(
    const float* __restrict__ feat_nhwc,
    const float* __restrict__ off,
    const float* __restrict__ wt,
    const float* __restrict__ g, const float* __restrict__ be,
    const float* __restrict__ m, const float* __restrict__ v,
    float* __restrict__ out_nhwc)
{
    constexpr int K  = C * 9;
    constexpr int KC = 32;
    constexpr int XP = KC + 1;
    constexpr int h  = (H - 1) / S + 1;
    constexpr int w  = (W - 1) / S + 1;
    constexpr int HW = h * w;
    constexpr int WN = O / 64;     // warps along N (1 or 2)
    constexpr int WM = 8 / WN;     // warps along M

    extern __shared__ float sm[];
    float* s_x  = sm;                       // TILE_M * XP
    float* s_w  = s_x + TILE_M * XP;        // KC * O
    float* s_mg = s_w + KC * O;             // TILE_M * 4
    int*   s_mi = (int*)(s_mg + TILE_M*4);  // TILE_M * 4

    int tid  = threadIdx.x;
    int gbase = blockIdx.x * TILE_M;

    int warp = tid >> 5, lane = tid & 31;
    int warpM = warp % WM, warpN = warp / WM;
    int mthr = lane & 3, nthr = lane >> 2;
    int tm0 = warpM*32 + mthr*8;
    int to0 = warpN*64 + nthr*4;

    unsigned long long acc[8][4];
    #pragma unroll
    for (int a = 0; a < 8; a++)
        #pragma unroll
        for (int bq = 0; bq < 4; bq++) acc[a][bq] = 0ull;

    int prev_n = -1;
    for (int k0 = 0; k0 < K; k0 += KC) {
        int n  = k0 / C;
        int c0 = k0 - n * C;
        __syncthreads();   // previous GEMM reads of s_x/s_w complete

        if (n != prev_n) {
            // phase A: bilinear metadata for tap n, all TILE_M positions
            for (int t = tid; t < TILE_M; t += 256) {
                int gpos = gbase + t;
                int b = gpos / HW, p = gpos - b*HW;
                int i = p / w, j = p - i*w;
                float offx = off[((size_t)(b*18 + n    ))*HW + p];
                float offy = off[((size_t)(b*18 + 9 + n))*HW + p];
                float px = (float)(i*S + (n/3)) + offx;
                float py = (float)(j*S + (n%3)) + offy;
                const float HB = (float)(H + 1), WB = (float)(W + 1);
                float qx0 = floorf(px);
                float fx0 = fminf(fmaxf(qx0,       0.f), HB);
                float fx1 = fminf(fmaxf(qx0 + 1.f, 0.f), HB);
                float pxc = fminf(fmaxf(px,        0.f), HB);
                float qy0 = floorf(py);
                float fy0 = fminf(fmaxf(qy0,       0.f), WB);
                float fy1 = fminf(fmaxf(qy0 + 1.f, 0.f), WB);
                float pyc = fminf(fmaxf(py,        0.f), WB);
                float glt = (1.f + (fx0 - pxc)) * (1.f + (fy0 - pyc));
                float grb = (1.f - (fx1 - pxc)) * (1.f - (fy1 - pyc));
                float glb = (1.f + (fx0 - pxc)) * (1.f - (fy1 - pyc));
                float grt = (1.f - (fx1 - pxc)) * (1.f + (fy0 - pyc));
                int x0 = (int)fx0, x1 = (int)fx1, y0 = (int)fy0, y1 = (int)fy1;
                bool bx0 = (x0 >= 1 && x0 <= H), bx1 = (x1 >= 1 && x1 <= H);
                bool by0 = (y0 >= 1 && y0 <= W), by1 = (y1 >= 1 && y1 <= W);
                int base = b * H * W * C;
                s_mg[t*4+0] = (bx0 && by0) ? glt : 0.f;
                s_mg[t*4+1] = (bx1 && by1) ? grb : 0.f;
                s_mg[t*4+2] = (bx0 && by1) ? glb : 0.f;
                s_mg[t*4+3] = (bx1 && by0) ? grt : 0.f;
                s_mi[t*4+0] = (bx0 && by0) ? base + ((x0-1)*W + (y0-1))*C : 0;
                s_mi[t*4+1] = (bx1 && by1) ? base + ((x1-1)*W + (y1-1))*C : 0;
                s_mi[t*4+2] = (bx0 && by1) ? base + ((x0-1)*W + (y1-1))*C : 0;
                s_mi[t*4+3] = (bx1 && by0) ? base + ((x1-1)*W + (y0-1))*C : 0;
            }
            prev_n = n;
            __syncthreads();
        }

        // gather: s_x[t][cc] for c = c0+cc
        #pragma unroll 4
        for (int idx = tid; idx < TILE_M*32; idx += 256) {
            int t = idx >> 5, cc = idx & 31;
            int c = c0 + cc;
            float g0 = s_mg[t*4+0], g1 = s_mg[t*4+1];
            float g2 = s_mg[t*4+2], g3 = s_mg[t*4+3];
            float val = g0 * feat_nhwc[s_mi[t*4+0] + c]
                      + g1 * feat_nhwc[s_mi[t*4+1] + c]
                      + g2 * feat_nhwc[s_mi[t*4+2] + c]
                      + g3 * feat_nhwc[s_mi[t*4+3] + c];
            s_x[t*XP + cc] = val;
        }
        // weights chunk: s_w[kk*O+o]
        const float4* wsrc = reinterpret_cast<const float4*>(wt + (size_t)k0*O);
        float4* wdst = reinterpret_cast<float4*>(s_w);
        #pragma unroll 2
        for (int idx = tid; idx < KC*O/4; idx += 256) wdst[idx] = wsrc[idx];
        __syncthreads();

        // GEMM over the chunk
        #pragma unroll 8
        for (int kk = 0; kk < KC; kk++) {
            float4 wa = *reinterpret_cast<const float4*>(&s_w[kk*O + to0]);
            float4 wb = *reinterpret_cast<const float4*>(&s_w[kk*O + to0 + 32]);
            unsigned long long wa01 = pk2(wa.x, wa.y), wa23 = pk2(wa.z, wa.w);
            unsigned long long wb01 = pk2(wb.x, wb.y), wb23 = pk2(wb.z, wb.w);
            #pragma unroll
            for (int jr = 0; jr < 8; jr++) {
                float xv = s_x[(tm0 + jr)*XP + kk];
                unsigned long long xd = pk2(xv, xv);
                fma2(acc[jr][0], xd, wa01);
                fma2(acc[jr][1], xd, wa23);
                fma2(acc[jr][2], xd, wb01);
                fma2(acc[jr][3], xd, wb23);
            }
        }
    }

    // epilogue: BN + ReLU, store NHWC (8 rows x 2 float4)
    float sc[8], sh[8];
    #pragma unroll
    for (int q = 0; q < 8; q++) {
        int o = to0 + ((q < 4) ? q : (28 + q));
        float s = g[o] / sqrtf(v[o] + 1e-5f);
        sc[q] = s;
        sh[q] = be[o] - m[o]*s;
    }
    #pragma unroll
    for (int jr = 0; jr < 8; jr++) {
        int gpos = gbase + tm0 + jr;
        float* op = out_nhwc + (size_t)gpos*O + to0;
        float2 a0 = upk2(acc[jr][0]), a1 = upk2(acc[jr][1]);
        float2 a2 = upk2(acc[jr][2]), a3 = upk2(acc[jr][3]);
        float4 r0, r1;
        r0.x = fmaxf(a0.x*sc[0] + sh[0], 0.f);
        r0.y = fmaxf(a0.y*sc[1] + sh[1], 0.f);
        r0.z = fmaxf(a1.x*sc[2] + sh[2], 0.f);
        r0.w = fmaxf(a1.y*sc[3] + sh[3], 0.f);
        r1.x = fmaxf(a2.x*sc[4] + sh[4], 0.f);
        r1.y = fmaxf(a2.y*sc[5] + sh[5], 0.f);
        r1.z = fmaxf(a3.x*sc[6] + sh[6], 0.f);
        r1.w = fmaxf(a3.y*sc[7] + sh[7], 0.f);
        *reinterpret_cast<float4*>(op)      = r0;
        *reinterpret_cast<float4*>(op + 32) = r1;
    }
}

// ---------------- global avg pool (8x8, NHWC) + FC (128 -> 100) ----------------
__global__ __launch_bounds__(128) void poolfc_kernel(
    const float* __restrict__ h4n,   // (B,8,8,128) NHWC
    const float* __restrict__ wcls, const float* __restrict__ bcls,
    float* __restrict__ out)
{
    __shared__ float s_p[128];
    int b = blockIdx.x, tid = threadIdx.x;
    const float* hb = h4n + (size_t)b * 64 * 128 + tid;
    float s = 0.f;
    #pragma unroll
    for (int k = 0; k < 64; k++) s += hb[k*128];
    s_p[tid] = s * (1.f / 64.f);
    __syncthreads();
    if (tid < 100) {
        float a = bcls[tid];
        const float* wr = wcls + tid*128;
        #pragma unroll 16
        for (int o = 0; o < 128; o++) a += s_p[o] * wr[o];
        out[b*100 + tid] = a;
    }
}

// ---------------- launch ----------------
extern "C" void kernel_launch(void* const* d_in, const int* in_sizes, int n_in,
                              void* d_out, int out_size)
{
    (void)in_sizes; (void)n_in; (void)out_size;
    const float* x    = (const float*)d_in[0];
    const float* w1   = (const float*)d_in[1];
    const float* b1   = (const float*)d_in[2];
    const float* g1   = (const float*)d_in[3];
    const float* be1  = (const float*)d_in[4];
    const float* m1   = (const float*)d_in[5];
    const float* v1   = (const float*)d_in[6];
    const float* wp2  = (const float*)d_in[7];
    const float* bp2  = (const float*)d_in[8];
    const float* wc2  = (const float*)d_in[9];
    const float* g2   = (const float*)d_in[10];
    const float* be2  = (const float*)d_in[11];
    const float* m2   = (const float*)d_in[12];
    const float* v2   = (const float*)d_in[13];
    const float* wp3  = (const float*)d_in[14];
    const float* bp3  = (const float*)d_in[15];
    const float* wc3  = (const float*)d_in[16];
    const float* g3   = (const float*)d_in[17];
    const float* be3  = (const float*)d_in[18];
    const float* m3   = (const float*)d_in[19];
    const float* v3   = (const float*)d_in[20];
    const float* wp4  = (const float*)d_in[21];
    const float* bp4  = (const float*)d_in[22];
    const float* wc4  = (const float*)d_in[23];
    const float* g4   = (const float*)d_in[24];
    const float* be4  = (const float*)d_in[25];
    const float* m4   = (const float*)d_in[26];
    const float* v4   = (const float*)d_in[27];
    const float* wcls = (const float*)d_in[28];
    const float* bcls = (const float*)d_in[29];
    float* out = (float*)d_out;

    float *h1n, *off2, *h2n, *off3, *h3n, *off4, *h4n, *wt2, *wt3, *wt4;
    cudaGetSymbolAddress((void**)&h1n, g_h1n);
    cudaGetSymbolAddress((void**)&off2,g_off2);
    cudaGetSymbolAddress((void**)&h2n, g_h2n);
    cudaGetSymbolAddress((void**)&off3,g_off3);
    cudaGetSymbolAddress((void**)&h3n, g_h3n);
    cudaGetSymbolAddress((void**)&off4,g_off4);
    cudaGetSymbolAddress((void**)&h4n, g_h4n);
    cudaGetSymbolAddress((void**)&wt2, g_wt2);
    cudaGetSymbolAddress((void**)&wt3, g_wt3);
    cudaGetSymbolAddress((void**)&wt4, g_wt4);

    // weight transposes (tiny)
    wprep_kernel<<<(288*64 +255)/256, 256>>>(wc2, wt2, 64, 32);
    wprep_kernel<<<(576*128+255)/256, 256>>>(wc3, wt3, 128, 64);
    wprep_kernel<<<(1152*128+255)/256, 256>>>(wc4, wt4, 128, 128);

    // L1
    conv1_kernel<<<NB*1024/256, 256>>>(x, w1, b1, g1, be1, m1, v1, h1n);

    // L2: 32 -> 64, stride 2 (32x32 -> 16x16)
    {
        size_t osm = 18*32*9*sizeof(float);
        offconv_v2<32,2,32,32><<<NB*256/32, 256, osm>>>(h1n, wp2, bp2, off2);
        constexpr int TM = 256, O = 64;
        size_t dsm = (size_t)(TM*33 + 32*O + TM*8) * sizeof(float);
        cudaFuncSetAttribute(deform_v2<32,64,2,32,32,TM>,
                             cudaFuncAttributeMaxDynamicSharedMemorySize, (int)dsm);
        deform_v2<32,64,2,32,32,TM><<<NB*256/TM, 256, dsm>>>(
            h1n, off2, wt2, g2, be2, m2, v2, h2n);
    }
    // L3: 64 -> 128, stride 1 (16x16)
    {
        size_t osm = 18*64*9*sizeof(float);
        offconv_v2<64,1,16,16><<<NB*256/32, 256, osm>>>(h2n, wp3, bp3, off3);
        constexpr int TM = 128, O = 128;
        size_t dsm = (size_t)(TM*33 + 32*O + TM*8) * sizeof(float);
        cudaFuncSetAttribute(deform_v2<64,128,1,16,16,TM>,
                             cudaFuncAttributeMaxDynamicSharedMemorySize, (int)dsm);
        deform_v2<64,128,1,16,16,TM><<<NB*256/TM, 256, dsm>>>(
            h2n, off3, wt3, g3, be3, m3, v3, h3n);
    }
    // L4: 128 -> 128, stride 2 (16x16 -> 8x8)
    {
        size_t osm = 18*128*9*sizeof(float);
        cudaFuncSetAttribute(offconv_v2<128,2,16,16>,
                             cudaFuncAttributeMaxDynamicSharedMemorySize, (int)osm);
        offconv_v2<128,2,16,16><<<NB*64/32, 256, osm>>>(h3n, wp4, bp4, off4);
        constexpr int TM = 128, O = 128;
        size_t dsm = (size_t)(TM*33 + 32*O + TM*8) * sizeof(float);
        cudaFuncSetAttribute(deform_v2<128,128,2,16,16,TM>,
                             cudaFuncAttributeMaxDynamicSharedMemorySize, (int)dsm);
        deform_v2<128,128,2,16,16,TM><<<NB*64/TM, 256, dsm>>>(
            h3n, off4, wt4, g4, be4, m4, v4, h4n);
    }
    // pool + FC
    poolfc_kernel<<<NB, 128>>>(h4n, wcls, bcls, out);
}

// round 3
// speedup vs baseline: 2.5262x; 1.5861x over previous
#include <cuda_runtime.h>
#include <cuda_bf16.h>
#include <cstdint>

#define NB 256   // batch

// ---------------- scratch (device globals; no allocation) ----------------
__device__ float g_h1n [(size_t)NB*32*32*32];   // NHWC
__device__ float g_off2[(size_t)NB*18*16*16];
__device__ float g_h2n [(size_t)NB*64*16*16];
__device__ float g_off3[(size_t)NB*18*16*16];
__device__ float g_h3n [(size_t)NB*128*16*16];
__device__ float g_off4[(size_t)NB*18*8*8];
__device__ float g_h4n [(size_t)NB*128*8*8];
__device__ __nv_bfloat16 g_wth2[64*288];        // wt_hi[k][o], k = n*C+c
__device__ __nv_bfloat16 g_wtl2[64*288];
__device__ __nv_bfloat16 g_wth3[128*576];
__device__ __nv_bfloat16 g_wtl3[128*576];
__device__ __nv_bfloat16 g_wth4[128*1152];
__device__ __nv_bfloat16 g_wtl4[128*1152];

// ---------------- small asm helpers ----------------
__device__ __forceinline__ unsigned long long pk2(float lo, float hi) {
    unsigned long long r;
    asm("mov.b64 %0, {%1, %2};" : "=l"(r) : "f"(lo), "f"(hi));
    return r;
}
__device__ __forceinline__ void fma2(unsigned long long& d,
                                     unsigned long long a, unsigned long long b) {
    asm("fma.rn.f32x2 %0, %1, %2, %0;" : "+l"(d) : "l"(a), "l"(b));
}
__device__ __forceinline__ unsigned long long add2(unsigned long long a,
                                                   unsigned long long b) {
    unsigned long long r;
    asm("add.rn.f32x2 %0, %1, %2;" : "=l"(r) : "l"(a), "l"(b));
    return r;
}
__device__ __forceinline__ float2 upk2(unsigned long long v) {
    float2 r;
    asm("mov.b64 {%0, %1}, %2;" : "=f"(r.x), "=f"(r.y) : "l"(v));
    return r;
}
__device__ __forceinline__ uint32_t cvt_bf16x2(float hi, float lo) {
    uint32_t r;
    asm("cvt.rn.bf16x2.f32 %0, %1, %2;" : "=r"(r) : "f"(hi), "f"(lo));
    return r;
}
__device__ __forceinline__ uint32_t sptr(const void* p) {
    return (uint32_t)__cvta_generic_to_shared(p);
}
__device__ __forceinline__ void ldsm4(uint32_t& r0, uint32_t& r1, uint32_t& r2,
                                      uint32_t& r3, uint32_t addr) {
    asm volatile("ldmatrix.sync.aligned.m8n8.x4.shared.b16 {%0,%1,%2,%3},[%4];"
                 : "=r"(r0), "=r"(r1), "=r"(r2), "=r"(r3) : "r"(addr));
}
__device__ __forceinline__ void ldsm4t(uint32_t& r0, uint32_t& r1, uint32_t& r2,
                                       uint32_t& r3, uint32_t addr) {
    asm volatile("ldmatrix.sync.aligned.m8n8.x4.trans.shared.b16 {%0,%1,%2,%3},[%4];"
                 : "=r"(r0), "=r"(r1), "=r"(r2), "=r"(r3) : "r"(addr));
}
__device__ __forceinline__ void mma16816(float* d, const uint32_t* a,
                                         uint32_t b0, uint32_t b1) {
    asm volatile(
        "mma.sync.aligned.m16n8k16.row.col.f32.bf16.bf16.f32 "
        "{%0,%1,%2,%3},{%4,%5,%6,%7},{%8,%9},{%0,%1,%2,%3};"
        : "+f"(d[0]), "+f"(d[1]), "+f"(d[2]), "+f"(d[3])
        : "r"(a[0]), "r"(a[1]), "r"(a[2]), "r"(a[3]), "r"(b0), "r"(b1));
}

// ---------------- weight split prep: wt[(n*C+c)*O+o] = wc[o][c][n] as bf16 hi/lo ----
__global__ void wprep_kernel(const float* __restrict__ wc,
                             __nv_bfloat16* __restrict__ wth,
                             __nv_bfloat16* __restrict__ wtl, int O, int C) {
    int idx = blockIdx.x * 256 + threadIdx.x;
    int K = C * 9;
    if (idx < K * O) {
        int k = idx / O, o = idx - k * O;
        int n = k / C,  c = k - n * C;
        float val = wc[(o * C + c) * 9 + n];
        __nv_bfloat16 hi = __float2bfloat16(val);
        wth[idx] = hi;
        wtl[idx] = __float2bfloat16(val - __bfloat162float(hi));
    }
}

// ---------------- conv1 (3->32, 3x3, pad 1) + BN + ReLU -> NHWC ----------------
__global__ __launch_bounds__(256) void conv1_kernel(
    const float* __restrict__ x, const float* __restrict__ w1, const float* __restrict__ b1,
    const float* __restrict__ g, const float* __restrict__ be,
    const float* __restrict__ m, const float* __restrict__ v,
    float* __restrict__ out_nhwc)
{
    __shared__ float s_w[32*27];
    __shared__ float s_sc[32], s_sh[32];
    __shared__ float s_o[256*33];

    int tid = threadIdx.x;
    for (int idx = tid; idx < 32*27; idx += 256) s_w[idx] = w1[idx];
    if (tid < 32) {
        float sc = g[tid] / sqrtf(v[tid] + 1e-5f);
        s_sc[tid] = sc;
        s_sh[tid] = be[tid] - m[tid]*sc + b1[tid]*sc;
    }
    __syncthreads();

    int q = blockIdx.x * 256 + tid;
    int b = q >> 10;
    int p = q & 1023;
    int i = p >> 5, j = p & 31;

    float in[27];
    const float* xb = x + (size_t)b * 3 * 1024;
    #pragma unroll
    for (int c = 0; c < 3; c++)
        #pragma unroll
        for (int ky = 0; ky < 3; ky++)
            #pragma unroll
            for (int kx = 0; kx < 3; kx++) {
                int yy = i - 1 + ky, xx = j - 1 + kx;
                float val = 0.f;
                if ((unsigned)yy < 32u && (unsigned)xx < 32u)
                    val = xb[c*1024 + yy*32 + xx];
                in[c*9 + ky*3 + kx] = val;
            }

    #pragma unroll
    for (int oc = 0; oc < 32; oc++) {
        float a = 0.f;
        #pragma unroll
        for (int k = 0; k < 27; k++) a += in[k] * s_w[oc*27 + k];
        s_o[tid*33 + oc] = fmaxf(a * s_sc[oc] + s_sh[oc], 0.f);
    }
    __syncthreads();

    size_t base = (size_t)blockIdx.x * 256 * 32;
    for (int idx = tid; idx < 256*32; idx += 256) {
        int pp = idx >> 5, oc = idx & 31;
        out_nhwc[base + idx] = s_o[pp*33 + oc];
    }
}

// ---------------- offset conv: NHWC feat, C -> 18, 3x3, pad 1, stride S ----------------
template<int C, int S, int H, int W>
__global__ __launch_bounds__(256) void offconv_v2(
    const float* __restrict__ feat_nhwc,
    const float* __restrict__ wp, const float* __restrict__ bp,
    float* __restrict__ off)
{
    constexpr int h = (H - 1) / S + 1;
    constexpr int w = (W - 1) / S + 1;
    constexpr int HW = h * w;

    extern __shared__ float s_w[];   // [(c*9+tap)*18 + ch]
    int tid = threadIdx.x;
    for (int idx = tid; idx < 18*C*9; idx += 256) {
        int ch = idx / (C*9);
        int r  = idx - ch * (C*9);
        s_w[r*18 + ch] = wp[idx];
    }
    __syncthreads();

    int pl = tid >> 3;
    int cg = tid & 7;
    int gpos = blockIdx.x * 32 + pl;
    int b = gpos / HW, p = gpos - b*HW;
    int i = p / w, j = p - i*w;
    const float* fb = feat_nhwc + (size_t)b * H * W * C;

    unsigned long long acc2[9];
    #pragma unroll
    for (int q = 0; q < 9; q++) acc2[q] = 0ull;

    #pragma unroll 2
    for (int ci = 0; ci < C/8; ci++) {
        int c = ci*8 + cg;
        float pv[9];
        #pragma unroll
        for (int ky = 0; ky < 3; ky++)
            #pragma unroll
            for (int kx = 0; kx < 3; kx++) {
                int yy = i*S - 1 + ky, xx = j*S - 1 + kx;
                float vv = 0.f;
                if ((unsigned)yy < (unsigned)H && (unsigned)xx < (unsigned)W)
                    vv = fb[((size_t)yy*W + xx)*C + c];
                pv[ky*3+kx] = vv;
            }
        const float* wr = s_w + c*162;
        #pragma unroll
        for (int tap = 0; tap < 9; tap++) {
            unsigned long long pd = pk2(pv[tap], pv[tap]);
            const unsigned long long* wv =
                reinterpret_cast<const unsigned long long*>(wr + tap*18);
            #pragma unroll
            for (int chp = 0; chp < 9; chp++) fma2(acc2[chp], pd, wv[chp]);
        }
    }

    #pragma unroll
    for (int d = 4; d >= 1; d >>= 1)
        #pragma unroll
        for (int q = 0; q < 9; q++)
            acc2[q] = add2(acc2[q], __shfl_xor_sync(0xffffffffu, acc2[q], d));

    if (cg == 0) {
        #pragma unroll
        for (int q = 0; q < 9; q++) {
            float2 r = upk2(acc2[q]);
            off[((size_t)(b*18 + 2*q    ))*HW + p] = r.x + bp[2*q];
            off[((size_t)(b*18 + 2*q + 1))*HW + p] = r.y + bp[2*q+1];
        }
    }
}

// ---------------- deform: gather + bf16x3 tensor-core GEMM + BN + ReLU -> NHWC ----
// feat_nhwc: (B,H,W,C); off: (B,18,h,w); wth/wtl: bf16 [k][O], k = n*C + c.
template<int C, int O, int S, int H, int W>
__global__ __launch_bounds__(256, 2) void deform_v3(
    const float* __restrict__ feat_nhwc,
    const float* __restrict__ off,
    const __nv_bfloat16* __restrict__ wth,
    const __nv_bfloat16* __restrict__ wtl,
    const float* __restrict__ g, const float* __restrict__ be,
    const float* __restrict__ m, const float* __restrict__ v,
    float* __restrict__ out_nhwc)
{
    constexpr int K   = C * 9;
    constexpr int KC  = 32;            // k-chunk
    constexpr int KP  = 40;            // padded A row (bf16)
    constexpr int NP  = O + 8;         // padded B row (bf16)
    constexpr int WN  = O / 64;        // warps along N
    constexpr int WM  = 8 / WN;        // warps along M
    constexpr int TILE_M = WM * 32;    // 256 (O=64) or 128 (O=128)
    constexpr int h   = (H - 1) / S + 1;
    constexpr int w   = (W - 1) / S + 1;
    constexpr int HW  = h * w;

    extern __shared__ char smem[];
    uint32_t* s_xh = (uint32_t*)smem;                       // TILE_M rows x 20 u32 (40 bf16)
    uint32_t* s_xl = s_xh + TILE_M*20;
    __nv_bfloat16* s_wh = (__nv_bfloat16*)(s_xl + TILE_M*20);   // KC x NP
    __nv_bfloat16* s_wl = s_wh + KC*NP;
    float* s_mg = (float*)(s_wl + KC*NP);                   // TILE_M*4
    int*   s_mi = (int*)(s_mg + TILE_M*4);                  // TILE_M*4
    float* s_sc = (float*)(s_mi + TILE_M*4);                // O
    float* s_sh = s_sc + O;                                 // O

    int tid = threadIdx.x;
    int gbase = blockIdx.x * TILE_M;
    int warp = tid >> 5, lane = tid & 31;
    int warpM = warp % WM, warpN = warp / WM;
    int tmw = warpM * 32;
    int to0 = warpN * 64;
    int lm = lane & 15, lh = lane >> 4;

    if (tid < O) {
        float s = g[tid] / sqrtf(v[tid] + 1e-5f);
        s_sc[tid] = s;
        s_sh[tid] = be[tid] - m[tid]*s;
    }

    uint32_t xh_s = sptr(s_xh), xl_s = sptr(s_xl);
    uint32_t wh_s = sptr(s_wh), wl_s = sptr(s_wl);
    // ldmatrix base addresses (per-warp invariant parts)
    uint32_t aab = ((tmw + lm)*KP + lh*8) * 2;                 // bytes into A tile
    uint32_t bab = (lm*NP + to0 + lh*8) * 2;                   // bytes into B tile

    float acc[2][8][4];
    #pragma unroll
    for (int f = 0; f < 2; f++)
        #pragma unroll
        for (int q = 0; q < 8; q++)
            #pragma unroll
            for (int r = 0; r < 4; r++) acc[f][q][r] = 0.f;

    int prev_n = -1;
    for (int k0 = 0; k0 < K; k0 += KC) {
        int n  = k0 / C;
        int c0 = k0 - n * C;
        __syncthreads();   // prior GEMM reads done; safe to overwrite tiles

        if (n != prev_n) {
            if (tid < TILE_M) {
                int t = tid;
                int gpos = gbase + t;
                int b = gpos / HW, p = gpos - b*HW;
                int i = p / w, j = p - i*w;
                float offx = off[((size_t)(b*18 + n    ))*HW + p];
                float offy = off[((size_t)(b*18 + 9 + n))*HW + p];
                float px = (float)(i*S + (n/3)) + offx;
                float py = (float)(j*S + (n%3)) + offy;
                const float HB = (float)(H + 1), WB = (float)(W + 1);
                float qx0 = floorf(px);
                float fx0 = fminf(fmaxf(qx0,       0.f), HB);
                float fx1 = fminf(fmaxf(qx0 + 1.f, 0.f), HB);
                float pxc = fminf(fmaxf(px,        0.f), HB);
                float qy0 = floorf(py);
                float fy0 = fminf(fmaxf(qy0,       0.f), WB);
                float fy1 = fminf(fmaxf(qy0 + 1.f, 0.f), WB);
                float pyc = fminf(fmaxf(py,        0.f), WB);
                float glt = (1.f + (fx0 - pxc)) * (1.f + (fy0 - pyc));
                float grb = (1.f - (fx1 - pxc)) * (1.f - (fy1 - pyc));
                float glb = (1.f + (fx0 - pxc)) * (1.f - (fy1 - pyc));
                float grt = (1.f - (fx1 - pxc)) * (1.f + (fy0 - pyc));
                int x0 = (int)fx0, x1 = (int)fx1, y0 = (int)fy0, y1 = (int)fy1;
                bool bx0 = (x0 >= 1 && x0 <= H), bx1 = (x1 >= 1 && x1 <= H);
                bool by0 = (y0 >= 1 && y0 <= W), by1 = (y1 >= 1 && y1 <= W);
                int base = b * H * W * C;
                s_mg[t*4+0] = (bx0 && by0) ? glt : 0.f;
                s_mg[t*4+1] = (bx1 && by1) ? grb : 0.f;
                s_mg[t*4+2] = (bx0 && by1) ? glb : 0.f;
                s_mg[t*4+3] = (bx1 && by0) ? grt : 0.f;
                s_mi[t*4+0] = (bx0 && by0) ? base + ((x0-1)*W + (y0-1))*C : 0;
                s_mi[t*4+1] = (bx1 && by1) ? base + ((x1-1)*W + (y1-1))*C : 0;
                s_mi[t*4+2] = (bx0 && by1) ? base + ((x0-1)*W + (y1-1))*C : 0;
                s_mi[t*4+3] = (bx1 && by0) ? base + ((x1-1)*W + (y0-1))*C : 0;
            }
            prev_n = n;
            __syncthreads();
        }

        // gather + bf16 hi/lo split: each thread handles 2 adjacent k
        #pragma unroll 2
        for (int idx = tid; idx < TILE_M*16; idx += 256) {
            int t = idx >> 4, cc2 = idx & 15;
            int c = c0 + cc2*2;
            float g0 = s_mg[t*4+0], g1 = s_mg[t*4+1];
            float g2 = s_mg[t*4+2], g3 = s_mg[t*4+3];
            const float2* p0 = (const float2*)(feat_nhwc + s_mi[t*4+0] + c);
            const float2* p1 = (const float2*)(feat_nhwc + s_mi[t*4+1] + c);
            const float2* p2 = (const float2*)(feat_nhwc + s_mi[t*4+2] + c);
            const float2* p3 = (const float2*)(feat_nhwc + s_mi[t*4+3] + c);
            float2 a0 = *p0, a1 = *p1, a2 = *p2, a3 = *p3;
            float v0 = g0*a0.x + g1*a1.x + g2*a2.x + g3*a3.x;
            float v1 = g0*a0.y + g1*a1.y + g2*a2.y + g3*a3.y;
            uint32_t hh = cvt_bf16x2(v1, v0);
            float h0f = __uint_as_float(hh << 16);
            float h1f = __uint_as_float(hh & 0xffff0000u);
            uint32_t ll = cvt_bf16x2(v1 - h1f, v0 - h0f);
            s_xh[t*20 + cc2] = hh;
            s_xl[t*20 + cc2] = ll;
        }
        // weights chunk copy (16B per thread-iter), rows padded to NP
        {
            constexpr int GPR = O / 8;      // 16B groups per row
            #pragma unroll
            for (int idx = tid; idx < KC*GPR; idx += 256) {
                int row = idx / GPR, gq = idx - row*GPR;
                const int4* sh_ = (const int4*)(wth + (size_t)(k0+row)*O + gq*8);
                const int4* sl_ = (const int4*)(wtl + (size_t)(k0+row)*O + gq*8);
                *(int4*)(s_wh + row*NP + gq*8) = *sh_;
                *(int4*)(s_wl + row*NP + gq*8) = *sl_;
            }
        }
        __syncthreads();

        // GEMM over the chunk: 2 k16-steps x 3 bf16 passes
        #pragma unroll
        for (int step = 0; step < 2; step++) {
            uint32_t koffA = (uint32_t)(step*16*2);
            uint32_t koffB = (uint32_t)(step*16*NP*2);
            uint32_t ah[2][4], al[2][4];
            #pragma unroll
            for (int f = 0; f < 2; f++) {
                uint32_t aoff = aab + (uint32_t)(f*16*KP*2) + koffA;
                ldsm4(ah[f][0], ah[f][1], ah[f][2], ah[f][3], xh_s + aoff);
                ldsm4(al[f][0], al[f][1], al[f][2], al[f][3], xl_s + aoff);
            }
            #pragma unroll
            for (int q16 = 0; q16 < 4; q16++) {
                uint32_t boff = bab + koffB + (uint32_t)(q16*16*2);
                uint32_t bh[4], bl[4];
                ldsm4t(bh[0], bh[1], bh[2], bh[3], wh_s + boff);
                ldsm4t(bl[0], bl[1], bl[2], bl[3], wl_s + boff);
                #pragma unroll
                for (int j = 0; j < 2; j++) {
                    uint32_t bh0 = bh[j*2], bh1 = bh[j*2+1];
                    uint32_t bl0 = bl[j*2], bl1 = bl[j*2+1];
                    #pragma unroll
                    for (int f = 0; f < 2; f++) {
                        float* d = acc[f][q16*2 + j];
                        mma16816(d, ah[f], bh0, bh1);
                        mma16816(d, ah[f], bl0, bl1);
                        mma16816(d, al[f], bh0, bh1);
                    }
                }
            }
        }
    }
    __syncthreads();

    // epilogue: BN + ReLU from register fragments
    int lq = lane >> 2, lr = lane & 3;
    #pragma unroll
    for (int f = 0; f < 2; f++) {
        #pragma unroll
        for (int q = 0; q < 8; q++) {
            int col = to0 + q*8 + lr*2;
            float sc0 = s_sc[col], sc1 = s_sc[col+1];
            float sh0 = s_sh[col], sh1 = s_sh[col+1];
            int row0 = gbase + tmw + f*16 + lq;
            int row1 = row0 + 8;
            float2 r0, r1;
            r0.x = fmaxf(acc[f][q][0]*sc0 + sh0, 0.f);
            r0.y = fmaxf(acc[f][q][1]*sc1 + sh1, 0.f);
            r1.x = fmaxf(acc[f][q][2]*sc0 + sh0, 0.f);
            r1.y = fmaxf(acc[f][q][3]*sc1 + sh1, 0.f);
            *(float2*)(out_nhwc + (size_t)row0*O + col) = r0;
            *(float2*)(out_nhwc + (size_t)row1*O + col) = r1;
        }
    }
}

// ---------------- global avg pool (8x8, NHWC) + FC (128 -> 100) ----------------
__global__ __launch_bounds__(128) void poolfc_kernel(
    const float* __restrict__ h4n,
    const float* __restrict__ wcls, const float* __restrict__ bcls,
    float* __restrict__ out)
{
    __shared__ float s_p[128];
    int b = blockIdx.x, tid = threadIdx.x;
    const float* hb = h4n + (size_t)b * 64 * 128 + tid;
    float s = 0.f;
    #pragma unroll
    for (int k = 0; k < 64; k++) s += hb[k*128];
    s_p[tid] = s * (1.f / 64.f);
    __syncthreads();
    if (tid < 100) {
        float a = bcls[tid];
        const float* wr = wcls + tid*128;
        #pragma unroll 16
        for (int o = 0; o < 128; o++) a += s_p[o] * wr[o];
        out[b*100 + tid] = a;
    }
}

// ---------------- launch ----------------
extern "C" void kernel_launch(void* const* d_in, const int* in_sizes, int n_in,
                              void* d_out, int out_size)
{
    (void)in_sizes; (void)n_in; (void)out_size;
    const float* x    = (const float*)d_in[0];
    const float* w1   = (const float*)d_in[1];
    const float* b1   = (const float*)d_in[2];
    const float* g1   = (const float*)d_in[3];
    const float* be1  = (const float*)d_in[4];
    const float* m1   = (const float*)d_in[5];
    const float* v1   = (const float*)d_in[6];
    const float* wp2  = (const float*)d_in[7];
    const float* bp2  = (const float*)d_in[8];
    const float* wc2  = (const float*)d_in[9];
    const float* g2   = (const float*)d_in[10];
    const float* be2  = (const float*)d_in[11];
    const float* m2   = (const float*)d_in[12];
    const float* v2   = (const float*)d_in[13];
    const float* wp3  = (const float*)d_in[14];
    const float* bp3  = (const float*)d_in[15];
    const float* wc3  = (const float*)d_in[16];
    const float* g3   = (const float*)d_in[17];
    const float* be3  = (const float*)d_in[18];
    const float* m3   = (const float*)d_in[19];
    const float* v3   = (const float*)d_in[20];
    const float* wp4  = (const float*)d_in[21];
    const float* bp4  = (const float*)d_in[22];
    const float* wc4  = (const float*)d_in[23];
    const float* g4   = (const float*)d_in[24];
    const float* be4  = (const float*)d_in[25];
    const float* m4   = (const float*)d_in[26];
    const float* v4   = (const float*)d_in[27];
    const float* wcls = (const float*)d_in[28];
    const float* bcls = (const float*)d_in[29];
    float* out = (float*)d_out;

    float *h1n, *off2, *h2n, *off3, *h3n, *off4, *h4n;
    __nv_bfloat16 *wth2, *wtl2, *wth3, *wtl3, *wth4, *wtl4;
    cudaGetSymbolAddress((void**)&h1n, g_h1n);
    cudaGetSymbolAddress((void**)&off2,g_off2);
    cudaGetSymbolAddress((void**)&h2n, g_h2n);
    cudaGetSymbolAddress((void**)&off3,g_off3);
    cudaGetSymbolAddress((void**)&h3n, g_h3n);
    cudaGetSymbolAddress((void**)&off4,g_off4);
    cudaGetSymbolAddress((void**)&h4n, g_h4n);
    cudaGetSymbolAddress((void**)&wth2, g_wth2);
    cudaGetSymbolAddress((void**)&wtl2, g_wtl2);
    cudaGetSymbolAddress((void**)&wth3, g_wth3);
    cudaGetSymbolAddress((void**)&wtl3, g_wtl3);
    cudaGetSymbolAddress((void**)&wth4, g_wth4);
    cudaGetSymbolAddress((void**)&wtl4, g_wtl4);

    // weight splits (tiny)
    wprep_kernel<<<(288*64 +255)/256, 256>>>(wc2, wth2, wtl2, 64, 32);
    wprep_kernel<<<(576*128+255)/256, 256>>>(wc3, wth3, wtl3, 128, 64);
    wprep_kernel<<<(1152*128+255)/256, 256>>>(wc4, wth4, wtl4, 128, 128);

    // L1
    conv1_kernel<<<NB*1024/256, 256>>>(x, w1, b1, g1, be1, m1, v1, h1n);

    // L2: 32 -> 64, stride 2 (32x32 -> 16x16), TILE_M=256
    {
        size_t osm = 18*32*9*sizeof(float);
        offconv_v2<32,2,32,32><<<NB*256/32, 256, osm>>>(h1n, wp2, bp2, off2);
        constexpr int TM = 256, O = 64;
        size_t dsm = (size_t)TM*20*4*2 + (size_t)32*(O+8)*2*2
                   + (size_t)TM*4*8 + (size_t)O*8;
        cudaFuncSetAttribute(deform_v3<32,64,2,32,32>,
                             cudaFuncAttributeMaxDynamicSharedMemorySize, (int)dsm);
        deform_v3<32,64,2,32,32><<<NB*256/TM, 256, dsm>>>(
            h1n, off2, wth2, wtl2, g2, be2, m2, v2, h2n);
    }
    // L3: 64 -> 128, stride 1 (16x16), TILE_M=128
    {
        size_t osm = 18*64*9*sizeof(float);
        offconv_v2<64,1,16,16><<<NB*256/32, 256, osm>>>(h2n, wp3, bp3, off3);
        constexpr int TM = 128, O = 128;
        size_t dsm = (size_t)TM*20*4*2 + (size_t)32*(O+8)*2*2
                   + (size_t)TM*4*8 + (size_t)O*8;
        cudaFuncSetAttribute(deform_v3<64,128,1,16,16>,
                             cudaFuncAttributeMaxDynamicSharedMemorySize, (int)dsm);
        deform_v3<64,128,1,16,16><<<NB*256/TM, 256, dsm>>>(
            h2n, off3, wth3, wtl3, g3, be3, m3, v3, h3n);
    }
    // L4: 128 -> 128, stride 2 (16x16 -> 8x8), TILE_M=128
    {
        size_t osm = 18*128*9*sizeof(float);
        cudaFuncSetAttribute(offconv_v2<128,2,16,16>,
                             cudaFuncAttributeMaxDynamicSharedMemorySize, (int)osm);
        offconv_v2<128,2,16,16><<<NB*64/32, 256, osm>>>(h3n, wp4, bp4, off4);
        constexpr int TM = 128, O = 128;
        size_t dsm = (size_t)TM*20*4*2 + (size_t)32*(O+8)*2*2
                   + (size_t)TM*4*8 + (size_t)O*8;
        cudaFuncSetAttribute(deform_v3<128,128,2,16,16>,
                             cudaFuncAttributeMaxDynamicSharedMemorySize, (int)dsm);
        deform_v3<128,128,2,16,16><<<NB*64/TM, 256, dsm>>>(
            h3n, off4, wth4, wtl4, g4, be4, m4, v4, h4n);
    }
    // pool + FC
    poolfc_kernel<<<NB, 128>>>(h4n, wcls, bcls, out);
}

// round 4
// speedup vs baseline: 2.5805x; 1.0215x over previous
#include <cuda_runtime.h>
#include <cuda_bf16.h>
#include <cstdint>

#define NB 256   // batch

// ---------------- scratch (device globals; no allocation) ----------------
__device__ float g_h1n [(size_t)NB*32*32*32];   // NHWC
__device__ float g_off2[(size_t)NB*16*16*18];   // position-major (b,hw,18)
__device__ float g_h2n [(size_t)NB*64*16*16];
__device__ float g_off3[(size_t)NB*16*16*18];
__device__ float g_h3n [(size_t)NB*128*16*16];
__device__ float g_off4[(size_t)NB*8*8*18];
__device__ float g_h4n [(size_t)NB*128*8*8];
__device__ __nv_bfloat16 g_wth2[64*288],  g_wtl2[64*288];    // deform weights [k][O]
__device__ __nv_bfloat16 g_wth3[128*576], g_wtl3[128*576];
__device__ __nv_bfloat16 g_wth4[128*1152],g_wtl4[128*1152];
__device__ __nv_bfloat16 g_wph2[288*40],  g_wpl2[288*40];    // offset weights [k][40]
__device__ __nv_bfloat16 g_wph3[576*40],  g_wpl3[576*40];
__device__ __nv_bfloat16 g_wph4[1152*40], g_wpl4[1152*40];

// ---------------- small asm helpers ----------------
__device__ __forceinline__ unsigned long long pk2(float lo, float hi) {
    unsigned long long r;
    asm("mov.b64 %0, {%1, %2};" : "=l"(r) : "f"(lo), "f"(hi));
    return r;
}
__device__ __forceinline__ void fma2(unsigned long long& d,
                                     unsigned long long a, unsigned long long b) {
    asm("fma.rn.f32x2 %0, %1, %2, %0;" : "+l"(d) : "l"(a), "l"(b));
}
__device__ __forceinline__ float2 upk2(unsigned long long v) {
    float2 r;
    asm("mov.b64 {%0, %1}, %2;" : "=f"(r.x), "=f"(r.y) : "l"(v));
    return r;
}
__device__ __forceinline__ uint32_t cvt_bf16x2(float hi, float lo) {
    uint32_t r;
    asm("cvt.rn.bf16x2.f32 %0, %1, %2;" : "=r"(r) : "f"(hi), "f"(lo));
    return r;
}
__device__ __forceinline__ uint32_t sptr(const void* p) {
    return (uint32_t)__cvta_generic_to_shared(p);
}
__device__ __forceinline__ void ldsm4(uint32_t& r0, uint32_t& r1, uint32_t& r2,
                                      uint32_t& r3, uint32_t addr) {
    asm volatile("ldmatrix.sync.aligned.m8n8.x4.shared.b16 {%0,%1,%2,%3},[%4];"
                 : "=r"(r0), "=r"(r1), "=r"(r2), "=r"(r3) : "r"(addr));
}
__device__ __forceinline__ void ldsm4t(uint32_t& r0, uint32_t& r1, uint32_t& r2,
                                       uint32_t& r3, uint32_t addr) {
    asm volatile("ldmatrix.sync.aligned.m8n8.x4.trans.shared.b16 {%0,%1,%2,%3},[%4];"
                 : "=r"(r0), "=r"(r1), "=r"(r2), "=r"(r3) : "r"(addr));
}
__device__ __forceinline__ void mma16816(float* d, const uint32_t* a,
                                         uint32_t b0, uint32_t b1) {
    asm volatile(
        "mma.sync.aligned.m16n8k16.row.col.f32.bf16.bf16.f32 "
        "{%0,%1,%2,%3},{%4,%5,%6,%7},{%8,%9},{%0,%1,%2,%3};"
        : "+f"(d[0]), "+f"(d[1]), "+f"(d[2]), "+f"(d[3])
        : "r"(a[0]), "r"(a[1]), "r"(a[2]), "r"(a[3]), "r"(b0), "r"(b1));
}
__device__ __forceinline__ void split_store(uint32_t* xh, uint32_t* xl, int idx,
                                            float v0, float v1) {
    uint32_t hh = cvt_bf16x2(v1, v0);
    float h0f = __uint_as_float(hh << 16);
    float h1f = __uint_as_float(hh & 0xffff0000u);
    uint32_t ll = cvt_bf16x2(v1 - h1f, v0 - h0f);
    xh[idx] = hh;
    xl[idx] = ll;
}

// ---------------- weight preps ----------------
// deform: wt[(n*C+c)*O+o] = wc[o][c][n], split hi/lo bf16
__global__ void wprep_kernel(const float* __restrict__ wc,
                             __nv_bfloat16* __restrict__ wth,
                             __nv_bfloat16* __restrict__ wtl, int O, int C) {
    int idx = blockIdx.x * 256 + threadIdx.x;
    int K = C * 9;
    if (idx < K * O) {
        int k = idx / O, o = idx - k * O;
        int n = k / C,  c = k - n * C;
        float val = wc[(o * C + c) * 9 + n];
        __nv_bfloat16 hi = __float2bfloat16(val);
        wth[idx] = hi;
        wtl[idx] = __float2bfloat16(val - __bfloat162float(hi));
    }
}
// offset: wpt[(n*C+c)*40+ch] = wp[ch][c][n] (ch<18, else 0), split hi/lo
__global__ void wprep_off(const float* __restrict__ wp,
                          __nv_bfloat16* __restrict__ wph,
                          __nv_bfloat16* __restrict__ wpl, int C) {
    int idx = blockIdx.x * 256 + threadIdx.x;
    int K = C * 9;
    if (idx < K * 40) {
        int k = idx / 40, ch = idx - k * 40;
        float val = 0.f;
        if (ch < 18) {
            int n = k / C, c = k - n * C;
            val = wp[(ch * C + c) * 9 + n];
        }
        __nv_bfloat16 hi = __float2bfloat16(val);
        wph[idx] = hi;
        wpl[idx] = __float2bfloat16(val - __bfloat162float(hi));
    }
}

// ---------------- conv1 (3->32, 3x3, pad 1) + BN + ReLU -> NHWC ----------------
__global__ __launch_bounds__(256) void conv1_kernel(
    const float* __restrict__ x, const float* __restrict__ w1, const float* __restrict__ b1,
    const float* __restrict__ g, const float* __restrict__ be,
    const float* __restrict__ m, const float* __restrict__ v,
    float* __restrict__ out_nhwc)
{
    __shared__ float s_w[32*27];
    __shared__ float s_sc[32], s_sh[32];
    __shared__ float s_o[256*33];

    int tid = threadIdx.x;
    for (int idx = tid; idx < 32*27; idx += 256) s_w[idx] = w1[idx];
    if (tid < 32) {
        float sc = g[tid] / sqrtf(v[tid] + 1e-5f);
        s_sc[tid] = sc;
        s_sh[tid] = be[tid] - m[tid]*sc + b1[tid]*sc;
    }
    __syncthreads();

    int q = blockIdx.x * 256 + tid;
    int b = q >> 10;
    int p = q & 1023;
    int i = p >> 5, j = p & 31;

    float in[27];
    const float* xb = x + (size_t)b * 3 * 1024;
    #pragma unroll
    for (int c = 0; c < 3; c++)
        #pragma unroll
        for (int ky = 0; ky < 3; ky++)
            #pragma unroll
            for (int kx = 0; kx < 3; kx++) {
                int yy = i - 1 + ky, xx = j - 1 + kx;
                float val = 0.f;
                if ((unsigned)yy < 32u && (unsigned)xx < 32u)
                    val = xb[c*1024 + yy*32 + xx];
                in[c*9 + ky*3 + kx] = val;
            }

    #pragma unroll
    for (int oc = 0; oc < 32; oc++) {
        float a = 0.f;
        #pragma unroll
        for (int k = 0; k < 27; k++) a += in[k] * s_w[oc*27 + k];
        s_o[tid*33 + oc] = fmaxf(a * s_sc[oc] + s_sh[oc], 0.f);
    }
    __syncthreads();

    size_t base = (size_t)blockIdx.x * 256 * 32;
    for (int idx = tid; idx < 256*32; idx += 256) {
        int pp = idx >> 5, oc = idx & 31;
        out_nhwc[base + idx] = s_o[pp*33 + oc];
    }
}

// ---------------- offconv_tc: 3x3 conv C->18 as bf16x3 tensor GEMM ----------------
// feat (B,H,W,C) NHWC -> off (B,hw,18) position-major. TILE_M=128, 8 warps (16 rows each).
template<int C, int S, int H, int W>
__global__ __launch_bounds__(256, 3) void offconv_tc(
    const float* __restrict__ feat_nhwc,
    const __nv_bfloat16* __restrict__ wph,
    const __nv_bfloat16* __restrict__ wpl,
    const float* __restrict__ bp,
    float* __restrict__ off)
{
    constexpr int K  = C * 9;
    constexpr int KC = 32;
    constexpr int NCH = K / KC;
    constexpr int TILE_M = 128;
    constexpr int KP = 40;          // padded A row (bf16)
    constexpr int NPB = 40;         // padded B row (bf16), 24 used
    constexpr int h  = (H - 1) / S + 1;
    constexpr int w  = (W - 1) / S + 1;
    constexpr int HW = h * w;

    extern __shared__ char smem[];
    int* s_ni = (int*)smem;                                   // TILE_M*9
    uint32_t* s_xa = (uint32_t*)(s_ni + TILE_M*9);            // [2][2][TILE_M*20]
    __nv_bfloat16* s_wb = (__nv_bfloat16*)(s_xa + 4*TILE_M*20); // [2][2][KC*NPB]
    float* s_bp = (float*)(s_wb + 4*KC*NPB);                  // 20

    int tid = threadIdx.x;
    int gbase = blockIdx.x * TILE_M;
    int warp = tid >> 5, lane = tid & 31;
    int tmw = warp * 16;
    int lm = lane & 15, lh = lane >> 4;

    if (tid < 18) s_bp[tid] = bp[tid];

    // neighbor indices for all 9 taps
    for (int e = tid; e < TILE_M*9; e += 256) {
        int t = e / 9, n = e - t*9;
        int gpos = gbase + t;
        int b = gpos / HW, p = gpos - b*HW;
        int i = p / w, j = p - i*w;
        int yy = i*S - 1 + n/3, xx = j*S - 1 + (n - (n/3)*3);
        s_ni[e] = ((unsigned)yy < (unsigned)H && (unsigned)xx < (unsigned)W)
                  ? b*H*W*C + (yy*W + xx)*C : -1;
    }
    __syncthreads();

    auto gatherA = [&](int k0, int buf) {
        int n = k0 / C, c0 = k0 - n*C;
        uint32_t* xh = s_xa + buf*(2*TILE_M*20);
        uint32_t* xl = xh + TILE_M*20;
        #pragma unroll 2
        for (int idx = tid; idx < TILE_M*16; idx += 256) {
            int t = idx >> 4, cc2 = idx & 15;
            int c = c0 + cc2*2;
            int ix = s_ni[t*9 + n];
            float2 v = make_float2(0.f, 0.f);
            if (ix >= 0) v = *(const float2*)(feat_nhwc + ix + c);
            split_store(xh, xl, t*20 + cc2, v.x, v.y);
        }
    };
    auto copyB = [&](int k0, int buf) {
        __nv_bfloat16* wh = s_wb + buf*(2*KC*NPB);
        __nv_bfloat16* wl = wh + KC*NPB;
        // 5 int4 per row (40 bf16 = 80B)
        for (int idx = tid; idx < KC*5; idx += 256) {
            int row = idx / 5, gq = idx - row*5;
            *(int4*)(wh + row*NPB + gq*8) = *(const int4*)(wph + (size_t)(k0+row)*40 + gq*8);
            *(int4*)(wl + row*NPB + gq*8) = *(const int4*)(wpl + (size_t)(k0+row)*40 + gq*8);
        }
    };

    float acc[3][4];
    #pragma unroll
    for (int q = 0; q < 3; q++)
        #pragma unroll
        for (int r = 0; r < 4; r++) acc[q][r] = 0.f;

    uint32_t aab = ((tmw + lm)*KP + lh*8) * 2;
    uint32_t bab = (lm*NPB + lh*8) * 2;

    gatherA(0, 0); copyB(0, 0);
    __syncthreads();

    for (int i = 0; i < NCH; i++) {
        int cur = i & 1;
        if (i + 1 < NCH) { gatherA((i+1)*KC, cur^1); copyB((i+1)*KC, cur^1); }

        uint32_t xh_s = sptr(s_xa + cur*(2*TILE_M*20));
        uint32_t xl_s = xh_s + TILE_M*20*4;
        uint32_t wh_s = sptr(s_wb + cur*(2*KC*NPB));
        uint32_t wl_s = wh_s + KC*NPB*2;

        #pragma unroll
        for (int step = 0; step < 2; step++) {
            uint32_t koffA = (uint32_t)(step*16*2);
            uint32_t koffB = (uint32_t)(step*16*NPB*2);
            uint32_t ah[4], al[4];
            ldsm4(ah[0], ah[1], ah[2], ah[3], xh_s + aab + koffA);
            ldsm4(al[0], al[1], al[2], al[3], xl_s + aab + koffA);
            #pragma unroll
            for (int q16 = 0; q16 < 2; q16++) {
                uint32_t boff = bab + koffB + (uint32_t)(q16*16*2);
                uint32_t bh[4], bl[4];
                ldsm4t(bh[0], bh[1], bh[2], bh[3], wh_s + boff);
                ldsm4t(bl[0], bl[1], bl[2], bl[3], wl_s + boff);
                int jmax = (q16 == 0) ? 2 : 1;   // cols 24+ are zero pad
                for (int j = 0; j < jmax; j++) {
                    float* d = acc[q16*2 + j];
                    mma16816(d, ah, bh[j*2], bh[j*2+1]);
                    mma16816(d, ah, bl[j*2], bl[j*2+1]);
                    mma16816(d, al, bh[j*2], bh[j*2+1]);
                }
            }
        }
        __syncthreads();
    }

    // epilogue: add bias, store (pos, 18)
    int lq = lane >> 2, lr = lane & 3;
    #pragma unroll
    for (int q = 0; q < 3; q++) {
        int col = q*8 + lr*2;
        if (col < 18) {
            float b0 = s_bp[col], b1 = s_bp[col+1];
            int row0 = gbase + tmw + lq;
            int row1 = row0 + 8;
            float2 r0 = make_float2(acc[q][0] + b0, acc[q][1] + b1);
            float2 r1 = make_float2(acc[q][2] + b0, acc[q][3] + b1);
            *(float2*)(off + (size_t)row0*18 + col) = r0;
            *(float2*)(off + (size_t)row1*18 + col) = r1;
        }
    }
}

// ---------------- deform: pipelined gather + bf16x3 tensor GEMM + BN + ReLU ----
// feat (B,H,W,C) NHWC; off (B,hw,18) pos-major; wth/wtl [k][O], k = n*C+c.
template<int C, int O, int S, int H, int W, int TILE_M, int WM, int WN, int FM>
__global__ __launch_bounds__(256, 2) void deform_v4(
    const float* __restrict__ feat_nhwc,
    const float* __restrict__ off,
    const __nv_bfloat16* __restrict__ wth,
    const __nv_bfloat16* __restrict__ wtl,
    const float* __restrict__ g, const float* __restrict__ be,
    const float* __restrict__ m, const float* __restrict__ v,
    float* __restrict__ out_nhwc)
{
    constexpr int K   = C * 9;
    constexpr int KC  = 32;
    constexpr int NCH = K / KC;
    constexpr int KP  = 40;            // padded A row (bf16)
    constexpr int NP  = O + 8;         // padded B row (bf16)
    constexpr int h   = (H - 1) / S + 1;
    constexpr int w   = (W - 1) / S + 1;
    constexpr int HW  = h * w;

    extern __shared__ char smem[];
    float* s_mg = (float*)smem;                               // TILE_M*9*4
    int*   s_mi = (int*)(s_mg + TILE_M*9*4);                  // TILE_M*9*4
    uint32_t* s_xa = (uint32_t*)(s_mi + TILE_M*9*4);          // [2][2][TILE_M*20]
    __nv_bfloat16* s_wb = (__nv_bfloat16*)(s_xa + 4*TILE_M*20); // [2][2][KC*NP]
    float* s_sc = (float*)(s_wb + 4*KC*NP);                   // O
    float* s_sh = s_sc + O;                                   // O

    int tid = threadIdx.x;
    int gbase = blockIdx.x * TILE_M;
    int warp = tid >> 5, lane = tid & 31;
    int warpM = warp % WM, warpN = warp / WM;
    int tmw = warpM * (16*FM);
    int to0 = warpN * 64;
    int lm = lane & 15, lh = lane >> 4;

    if (tid < O) {
        float s = g[tid] / sqrtf(v[tid] + 1e-5f);
        s_sc[tid] = s;
        s_sh[tid] = be[tid] - m[tid]*s;
    }

    // ---- bilinear metadata for ALL 9 taps, once ----
    for (int e = tid; e < TILE_M*9; e += 256) {
        int t = e / 9, n = e - t*9;
        int gpos = gbase + t;
        int b = gpos / HW, p = gpos - b*HW;
        int i = p / w, j = p - i*w;
        float offx = off[(size_t)gpos*18 + n];
        float offy = off[(size_t)gpos*18 + 9 + n];
        float px = (float)(i*S + (n/3)) + offx;
        float py = (float)(j*S + (n - (n/3)*3)) + offy;
        const float HB = (float)(H + 1), WB = (float)(W + 1);
        float qx0 = floorf(px);
        float fx0 = fminf(fmaxf(qx0,       0.f), HB);
        float fx1 = fminf(fmaxf(qx0 + 1.f, 0.f), HB);
        float pxc = fminf(fmaxf(px,        0.f), HB);
        float qy0 = floorf(py);
        float fy0 = fminf(fmaxf(qy0,       0.f), WB);
        float fy1 = fminf(fmaxf(qy0 + 1.f, 0.f), WB);
        float pyc = fminf(fmaxf(py,        0.f), WB);
        float glt = (1.f + (fx0 - pxc)) * (1.f + (fy0 - pyc));
        float grb = (1.f - (fx1 - pxc)) * (1.f - (fy1 - pyc));
        float glb = (1.f + (fx0 - pxc)) * (1.f - (fy1 - pyc));
        float grt = (1.f - (fx1 - pxc)) * (1.f + (fy0 - pyc));
        int x0 = (int)fx0, x1 = (int)fx1, y0 = (int)fy0, y1 = (int)fy1;
        bool bx0 = (x0 >= 1 && x0 <= H), bx1 = (x1 >= 1 && x1 <= H);
        bool by0 = (y0 >= 1 && y0 <= W), by1 = (y1 >= 1 && y1 <= W);
        int base = b * H * W * C;
        s_mg[e*4+0] = (bx0 && by0) ? glt : 0.f;
        s_mg[e*4+1] = (bx1 && by1) ? grb : 0.f;
        s_mg[e*4+2] = (bx0 && by1) ? glb : 0.f;
        s_mg[e*4+3] = (bx1 && by0) ? grt : 0.f;
        s_mi[e*4+0] = (bx0 && by0) ? base + ((x0-1)*W + (y0-1))*C : 0;
        s_mi[e*4+1] = (bx1 && by1) ? base + ((x1-1)*W + (y1-1))*C : 0;
        s_mi[e*4+2] = (bx0 && by1) ? base + ((x0-1)*W + (y1-1))*C : 0;
        s_mi[e*4+3] = (bx1 && by0) ? base + ((x1-1)*W + (y0-1))*C : 0;
    }
    __syncthreads();

    auto gatherA = [&](int k0, int buf) {
        int n = k0 / C, c0 = k0 - n*C;
        uint32_t* xh = s_xa + buf*(2*TILE_M*20);
        uint32_t* xl = xh + TILE_M*20;
        #pragma unroll 2
        for (int idx = tid; idx < TILE_M*16; idx += 256) {
            int t = idx >> 4, cc2 = idx & 15;
            int c = c0 + cc2*2;
            const float4 g4 = *(const float4*)(s_mg + (t*9+n)*4);
            const int4   i4 = *(const int4*)(s_mi + (t*9+n)*4);
            unsigned long long a = 0ull;
            fma2(a, pk2(g4.x, g4.x), *(const unsigned long long*)(feat_nhwc + i4.x + c));
            fma2(a, pk2(g4.y, g4.y), *(const unsigned long long*)(feat_nhwc + i4.y + c));
            fma2(a, pk2(g4.z, g4.z), *(const unsigned long long*)(feat_nhwc + i4.z + c));
            fma2(a, pk2(g4.w, g4.w), *(const unsigned long long*)(feat_nhwc + i4.w + c));
            float2 vv = upk2(a);
            split_store(xh, xl, t*20 + cc2, vv.x, vv.y);
        }
    };
    auto copyB = [&](int k0, int buf) {
        __nv_bfloat16* wh = s_wb + buf*(2*KC*NP);
        __nv_bfloat16* wl = wh + KC*NP;
        constexpr int GPR = O / 8;
        for (int idx = tid; idx < KC*GPR; idx += 256) {
            int row = idx / GPR, gq = idx - row*GPR;
            *(int4*)(wh + row*NP + gq*8) = *(const int4*)(wth + (size_t)(k0+row)*O + gq*8);
            *(int4*)(wl + row*NP + gq*8) = *(const int4*)(wtl + (size_t)(k0+row)*O + gq*8);
        }
    };

    float acc[FM][8][4];
    #pragma unroll
    for (int f = 0; f < FM; f++)
        #pragma unroll
        for (int q = 0; q < 8; q++)
            #pragma unroll
            for (int r = 0; r < 4; r++) acc[f][q][r] = 0.f;

    uint32_t aab = ((tmw + lm)*KP + lh*8) * 2;
    uint32_t bab = (lm*NP + to0 + lh*8) * 2;

    gatherA(0, 0); copyB(0, 0);
    __syncthreads();

    for (int i = 0; i < NCH; i++) {
        int cur = i & 1;
        if (i + 1 < NCH) { gatherA((i+1)*KC, cur^1); copyB((i+1)*KC, cur^1); }

        uint32_t xh_s = sptr(s_xa + cur*(2*TILE_M*20));
        uint32_t xl_s = xh_s + TILE_M*20*4;
        uint32_t wh_s = sptr(s_wb + cur*(2*KC*NP));
        uint32_t wl_s = wh_s + KC*NP*2;

        #pragma unroll
        for (int step = 0; step < 2; step++) {
            uint32_t koffA = (uint32_t)(step*16*2);
            uint32_t koffB = (uint32_t)(step*16*NP*2);
            uint32_t ah[FM][4], al[FM][4];
            #pragma unroll
            for (int f = 0; f < FM; f++) {
                uint32_t aoff = aab + (uint32_t)(f*16*KP*2) + koffA;
                ldsm4(ah[f][0], ah[f][1], ah[f][2], ah[f][3], xh_s + aoff);
                ldsm4(al[f][0], al[f][1], al[f][2], al[f][3], xl_s + aoff);
            }
            #pragma unroll
            for (int q16 = 0; q16 < 4; q16++) {
                uint32_t boff = bab + koffB + (uint32_t)(q16*16*2);
                uint32_t bh[4], bl[4];
                ldsm4t(bh[0], bh[1], bh[2], bh[3], wh_s + boff);
                ldsm4t(bl[0], bl[1], bl[2], bl[3], wl_s + boff);
                #pragma unroll
                for (int j = 0; j < 2; j++) {
                    uint32_t bh0 = bh[j*2], bh1 = bh[j*2+1];
                    uint32_t bl0 = bl[j*2], bl1 = bl[j*2+1];
                    #pragma unroll
                    for (int f = 0; f < FM; f++) {
                        float* d = acc[f][q16*2 + j];
                        mma16816(d, ah[f], bh0, bh1);
                        mma16816(d, ah[f], bl0, bl1);
                        mma16816(d, al[f], bh0, bh1);
                    }
                }
            }
        }
        __syncthreads();
    }

    // epilogue: BN + ReLU from register fragments
    int lq = lane >> 2, lr = lane & 3;
    #pragma unroll
    for (int f = 0; f < FM; f++) {
        #pragma unroll
        for (int q = 0; q < 8; q++) {
            int col = to0 + q*8 + lr*2;
            float sc0 = s_sc[col], sc1 = s_sc[col+1];
            float sh0 = s_sh[col], sh1 = s_sh[col+1];
            int row0 = gbase + tmw + f*16 + lq;
            int row1 = row0 + 8;
            float2 r0, r1;
            r0.x = fmaxf(acc[f][q][0]*sc0 + sh0, 0.f);
            r0.y = fmaxf(acc[f][q][1]*sc1 + sh1, 0.f);
            r1.x = fmaxf(acc[f][q][2]*sc0 + sh0, 0.f);
            r1.y = fmaxf(acc[f][q][3]*sc1 + sh1, 0.f);
            *(float2*)(out_nhwc + (size_t)row0*O + col) = r0;
            *(float2*)(out_nhwc + (size_t)row1*O + col) = r1;
        }
    }
}

// ---------------- global avg pool (8x8, NHWC) + FC (128 -> 100) ----------------
__global__ __launch_bounds__(128) void poolfc_kernel(
    const float* __restrict__ h4n,
    const float* __restrict__ wcls, const float* __restrict__ bcls,
    float* __restrict__ out)
{
    __shared__ float s_p[128];
    int b = blockIdx.x, tid = threadIdx.x;
    const float* hb = h4n + (size_t)b * 64 * 128 + tid;
    float s = 0.f;
    #pragma unroll
    for (int k = 0; k < 64; k++) s += hb[k*128];
    s_p[tid] = s * (1.f / 64.f);
    __syncthreads();
    if (tid < 100) {
        float a = bcls[tid];
        const float* wr = wcls + tid*128;
        #pragma unroll 16
        for (int o = 0; o < 128; o++) a += s_p[o] * wr[o];
        out[b*100 + tid] = a;
    }
}

// ---------------- launch ----------------
extern "C" void kernel_launch(void* const* d_in, const int* in_sizes, int n_in,
                              void* d_out, int out_size)
{
    (void)in_sizes; (void)n_in; (void)out_size;
    const float* x    = (const float*)d_in[0];
    const float* w1   = (const float*)d_in[1];
    const float* b1   = (const float*)d_in[2];
    const float* g1   = (const float*)d_in[3];
    const float* be1  = (const float*)d_in[4];
    const float* m1   = (const float*)d_in[5];
    const float* v1   = (const float*)d_in[6];
    const float* wp2  = (const float*)d_in[7];
    const float* bp2  = (const float*)d_in[8];
    const float* wc2  = (const float*)d_in[9];
    const float* g2   = (const float*)d_in[10];
    const float* be2  = (const float*)d_in[11];
    const float* m2   = (const float*)d_in[12];
    const float* v2   = (const float*)d_in[13];
    const float* wp3  = (const float*)d_in[14];
    const float* bp3  = (const float*)d_in[15];
    const float* wc3  = (const float*)d_in[16];
    const float* g3   = (const float*)d_in[17];
    const float* be3  = (const float*)d_in[18];
    const float* m3   = (const float*)d_in[19];
    const float* v3   = (const float*)d_in[20];
    const float* wp4  = (const float*)d_in[21];
    const float* bp4  = (const float*)d_in[22];
    const float* wc4  = (const float*)d_in[23];
    const float* g4   = (const float*)d_in[24];
    const float* be4  = (const float*)d_in[25];
    const float* m4   = (const float*)d_in[26];
    const float* v4   = (const float*)d_in[27];
    const float* wcls = (const float*)d_in[28];
    const float* bcls = (const float*)d_in[29];
    float* out = (float*)d_out;

    float *h1n, *off2, *h2n, *off3, *h3n, *off4, *h4n;
    __nv_bfloat16 *wth2, *wtl2, *wth3, *wtl3, *wth4, *wtl4;
    __nv_bfloat16 *wph2, *wpl2, *wph3, *wpl3, *wph4, *wpl4;
    cudaGetSymbolAddress((void**)&h1n, g_h1n);
    cudaGetSymbolAddress((void**)&off2,g_off2);
    cudaGetSymbolAddress((void**)&h2n, g_h2n);
    cudaGetSymbolAddress((void**)&off3,g_off3);
    cudaGetSymbolAddress((void**)&h3n, g_h3n);
    cudaGetSymbolAddress((void**)&off4,g_off4);
    cudaGetSymbolAddress((void**)&h4n, g_h4n);
    cudaGetSymbolAddress((void**)&wth2, g_wth2);
    cudaGetSymbolAddress((void**)&wtl2, g_wtl2);
    cudaGetSymbolAddress((void**)&wth3, g_wth3);
    cudaGetSymbolAddress((void**)&wtl3, g_wtl3);
    cudaGetSymbolAddress((void**)&wth4, g_wth4);
    cudaGetSymbolAddress((void**)&wtl4, g_wtl4);
    cudaGetSymbolAddress((void**)&wph2, g_wph2);
    cudaGetSymbolAddress((void**)&wpl2, g_wpl2);
    cudaGetSymbolAddress((void**)&wph3, g_wph3);
    cudaGetSymbolAddress((void**)&wpl3, g_wpl3);
    cudaGetSymbolAddress((void**)&wph4, g_wph4);
    cudaGetSymbolAddress((void**)&wpl4, g_wpl4);

    // weight preps (tiny)
    wprep_kernel<<<(288*64 +255)/256, 256>>>(wc2, wth2, wtl2, 64, 32);
    wprep_kernel<<<(576*128+255)/256, 256>>>(wc3, wth3, wtl3, 128, 64);
    wprep_kernel<<<(1152*128+255)/256, 256>>>(wc4, wth4, wtl4, 128, 128);
    wprep_off<<<(288*40 +255)/256, 256>>>(wp2, wph2, wpl2, 32);
    wprep_off<<<(576*40 +255)/256, 256>>>(wp3, wph3, wpl3, 64);
    wprep_off<<<(1152*40+255)/256, 256>>>(wp4, wph4, wpl4, 128);

    // L1
    conv1_kernel<<<NB*1024/256, 256>>>(x, w1, b1, g1, be1, m1, v1, h1n);

    // shared-mem sizes
    auto off_dsm = [](int TM) {
        return (size_t)TM*9*4 + (size_t)4*TM*20*4 + (size_t)4*32*40*2 + 80;
    };
    auto def_dsm = [](int TM, int O) {
        return (size_t)TM*9*4*8 + (size_t)4*TM*20*4 + (size_t)4*32*(O+8)*2
             + (size_t)O*8;
    };

    // L2: 32 -> 64, stride 2 (32x32 -> 16x16)
    {
        size_t osm = off_dsm(128);
        cudaFuncSetAttribute(offconv_tc<32,2,32,32>,
                             cudaFuncAttributeMaxDynamicSharedMemorySize, (int)osm);
        offconv_tc<32,2,32,32><<<NB*256/128, 256, osm>>>(h1n, wph2, wpl2, bp2, off2);
        size_t dsm = def_dsm(128, 64);
        cudaFuncSetAttribute(deform_v4<32,64,2,32,32,128,8,1,1>,
                             cudaFuncAttributeMaxDynamicSharedMemorySize, (int)dsm);
        deform_v4<32,64,2,32,32,128,8,1,1><<<NB*256/128, 256, dsm>>>(
            h1n, off2, wth2, wtl2, g2, be2, m2, v2, h2n);
    }
    // L3: 64 -> 128, stride 1 (16x16)
    {
        size_t osm = off_dsm(128);
        cudaFuncSetAttribute(offconv_tc<64,1,16,16>,
                             cudaFuncAttributeMaxDynamicSharedMemorySize, (int)osm);
        offconv_tc<64,1,16,16><<<NB*256/128, 256, osm>>>(h2n, wph3, wpl3, bp3, off3);
        size_t dsm = def_dsm(128, 128);
        cudaFuncSetAttribute(deform_v4<64,128,1,16,16,128,4,2,2>,
                             cudaFuncAttributeMaxDynamicSharedMemorySize, (int)dsm);
        deform_v4<64,128,1,16,16,128,4,2,2><<<NB*256/128, 256, dsm>>>(
            h2n, off3, wth3, wtl3, g3, be3, m3, v3, h3n);
    }
    // L4: 128 -> 128, stride 2 (16x16 -> 8x8)
    {
        size_t osm = off_dsm(128);
        cudaFuncSetAttribute(offconv_tc<128,2,16,16>,
                             cudaFuncAttributeMaxDynamicSharedMemorySize, (int)osm);
        offconv_tc<128,2,16,16><<<NB*64/128, 256, osm>>>(h3n, wph4, wpl4, bp4, off4);
        size_t dsm = def_dsm(64, 128);
        cudaFuncSetAttribute(deform_v4<128,128,2,16,16,64,4,2,1>,
                             cudaFuncAttributeMaxDynamicSharedMemorySize, (int)dsm);
        deform_v4<128,128,2,16,16,64,4,2,1><<<NB*64/64, 256, dsm>>>(
            h3n, off4, wth4, wtl4, g4, be4, m4, v4, h4n);
    }
    // pool + FC
    poolfc_kernel<<<NB, 128>>>(h4n, wcls, bcls, out);
}